// round 2
// baseline (speedup 1.0000x reference)
#include <cuda_runtime.h>
#include <math.h>

// Problem constants
#define BATCH 4
#define SEQ   1024
#define DIM   512
#define HEADS 8
#define HDIM  64
#define FF    2048
#define ROWS  (BATCH*SEQ)          // 4096
#define BH    (BATCH*HEADS)        // 32
#define EPSLN 1e-5f

// ---------------- scratch (device globals; no allocation allowed) ----------------
__device__ float g_q  [BH*SEQ*HDIM];     // (b,h,s,hd)
__device__ float g_k  [BH*SEQ*HDIM];
__device__ float g_v  [BH*SEQ*HDIM];
__device__ float g_ao [ROWS*DIM];        // attn out in (b,s,d)
__device__ float g_t1 [ROWS*DIM];        // x + attn@Wo+bo
__device__ float g_h  [ROWS*DIM];        // LN1 output
__device__ float g_hid[ROWS*FF];         // elu(h@W1+b1)
__device__ float g_h2 [ROWS*DIM];        // hid@W2+b2
__device__ float g_g  [ROWS*2*DIM];      // h2@Wg+bg

// =====================================================================
// Generic SGEMM: C[M,N] = A[M,K] @ B[K,N] + bias, 128x128x16 tiles,
// 256 threads, 8x8 per thread. EPI: 0=plain, 1=ELU, 2=+resid
// =====================================================================
template<int EPI>
__global__ __launch_bounds__(256)
void sgemm_kernel(const float* __restrict__ A, const float* __restrict__ B,
                  const float* __restrict__ bias, const float* __restrict__ resid,
                  float* __restrict__ C, int M, int N, int K)
{
    __shared__ float As[16][128];
    __shared__ float Bs[16][128];
    const int tid  = threadIdx.x;
    const int row0 = blockIdx.y * 128;
    const int col0 = blockIdx.x * 128;

    // A: 128 rows x 16 cols per tile -> 2 float4 per thread
    const int arow = tid >> 1, acol = (tid & 1) * 8;
    // B: 16 rows x 128 cols per tile -> 2 float4 per thread
    const int brow = tid >> 4, bcol = (tid & 15) * 8;
    const int ty = tid >> 4, tx = tid & 15;

    const float* Ap = A + (size_t)(row0 + arow) * K + acol;
    const float* Bp = B + (size_t)brow * N + col0 + bcol;

    float acc[8][8];
#pragma unroll
    for (int i = 0; i < 8; i++)
#pragma unroll
        for (int j = 0; j < 8; j++) acc[i][j] = 0.f;

    for (int kt = 0; kt < K; kt += 16) {
        float4 a0 = *(const float4*)Ap;
        float4 a1 = *(const float4*)(Ap + 4);
        Ap += 16;
        As[acol+0][arow] = a0.x; As[acol+1][arow] = a0.y;
        As[acol+2][arow] = a0.z; As[acol+3][arow] = a0.w;
        As[acol+4][arow] = a1.x; As[acol+5][arow] = a1.y;
        As[acol+6][arow] = a1.z; As[acol+7][arow] = a1.w;
        *(float4*)&Bs[brow][bcol]   = *(const float4*)Bp;
        *(float4*)&Bs[brow][bcol+4] = *(const float4*)(Bp + 4);
        Bp += (size_t)16 * N;
        __syncthreads();
#pragma unroll
        for (int kk = 0; kk < 16; kk++) {
            float af[8], bf[8];
            *(float4*)&af[0] = *(const float4*)&As[kk][ty*8];
            *(float4*)&af[4] = *(const float4*)&As[kk][ty*8+4];
            *(float4*)&bf[0] = *(const float4*)&Bs[kk][tx*8];
            *(float4*)&bf[4] = *(const float4*)&Bs[kk][tx*8+4];
#pragma unroll
            for (int i = 0; i < 8; i++)
#pragma unroll
                for (int j = 0; j < 8; j++) acc[i][j] += af[i] * bf[j];
        }
        __syncthreads();
    }

#pragma unroll
    for (int i = 0; i < 8; i++) {
        int r = row0 + ty*8 + i;
#pragma unroll
        for (int j0 = 0; j0 < 8; j0 += 4) {
            int c = col0 + tx*8 + j0;
            float4 v;
            v.x = acc[i][j0+0] + bias[c+0];
            v.y = acc[i][j0+1] + bias[c+1];
            v.z = acc[i][j0+2] + bias[c+2];
            v.w = acc[i][j0+3] + bias[c+3];
            if (EPI == 1) {  // ELU
                v.x = v.x > 0.f ? v.x : expm1f(v.x);
                v.y = v.y > 0.f ? v.y : expm1f(v.y);
                v.z = v.z > 0.f ? v.z : expm1f(v.z);
                v.w = v.w > 0.f ? v.w : expm1f(v.w);
            }
            if (EPI == 2) {  // + residual (same M,N layout)
                float4 rr = *(const float4*)&resid[(size_t)r*N + c];
                v.x += rr.x; v.y += rr.y; v.z += rr.z; v.w += rr.w;
            }
            *(float4*)&C[(size_t)r*N + c] = v;
        }
    }
}

// =====================================================================
// Fused QKV GEMM: x(4096,512) @ {Wq,Wk,Wv}, epilogue remap to (b,h,s,hd)
// grid = (12, 32): bx 0-3 -> Q, 4-7 -> K, 8-11 -> V. 128x128x16 tiles.
// =====================================================================
__global__ __launch_bounds__(256)
void qkv_kernel(const float* __restrict__ A,
                const float* __restrict__ Wq, const float* __restrict__ Wk,
                const float* __restrict__ Wv,
                const float* __restrict__ bq, const float* __restrict__ bk,
                const float* __restrict__ bv)
{
    __shared__ float As[16][128];
    __shared__ float Bs[16][128];
    const int tid  = threadIdx.x;
    const int n0   = blockIdx.x * 128;
    const int which = n0 >> 9;                      // 0,1,2
    const float* W    = (which == 0) ? Wq : (which == 1) ? Wk : Wv;
    const float* bias = (which == 0) ? bq : (which == 1) ? bk : bv;
    float*       OUT  = (which == 0) ? g_q : (which == 1) ? g_k : g_v;
    const int nloc0 = n0 & 511;
    const int row0  = blockIdx.y * 128;

    const int arow = tid >> 1, acol = (tid & 1) * 8;
    const int brow = tid >> 4, bcol = (tid & 15) * 8;
    const int ty = tid >> 4, tx = tid & 15;

    const float* Ap = A + (size_t)(row0 + arow) * DIM + acol;
    const float* Bp = W + (size_t)brow * DIM + nloc0 + bcol;

    float acc[8][8];
#pragma unroll
    for (int i = 0; i < 8; i++)
#pragma unroll
        for (int j = 0; j < 8; j++) acc[i][j] = 0.f;

    for (int kt = 0; kt < DIM; kt += 16) {
        float4 a0 = *(const float4*)Ap;
        float4 a1 = *(const float4*)(Ap + 4);
        Ap += 16;
        As[acol+0][arow] = a0.x; As[acol+1][arow] = a0.y;
        As[acol+2][arow] = a0.z; As[acol+3][arow] = a0.w;
        As[acol+4][arow] = a1.x; As[acol+5][arow] = a1.y;
        As[acol+6][arow] = a1.z; As[acol+7][arow] = a1.w;
        *(float4*)&Bs[brow][bcol]   = *(const float4*)Bp;
        *(float4*)&Bs[brow][bcol+4] = *(const float4*)(Bp + 4);
        Bp += 16 * DIM;
        __syncthreads();
#pragma unroll
        for (int kk = 0; kk < 16; kk++) {
            float af[8], bf[8];
            *(float4*)&af[0] = *(const float4*)&As[kk][ty*8];
            *(float4*)&af[4] = *(const float4*)&As[kk][ty*8+4];
            *(float4*)&bf[0] = *(const float4*)&Bs[kk][tx*8];
            *(float4*)&bf[4] = *(const float4*)&Bs[kk][tx*8+4];
#pragma unroll
            for (int i = 0; i < 8; i++)
#pragma unroll
                for (int j = 0; j < 8; j++) acc[i][j] += af[i] * bf[j];
        }
        __syncthreads();
    }

#pragma unroll
    for (int i = 0; i < 8; i++) {
        int m = row0 + ty*8 + i;
        int b = m >> 10, s = m & 1023;
#pragma unroll
        for (int j0 = 0; j0 < 8; j0 += 4) {
            int n = nloc0 + tx*8 + j0;          // within [0,512)
            int h = n >> 6, hd = n & 63;        // h constant across the float4
            float4 v;
            v.x = acc[i][j0+0] + bias[n+0];
            v.y = acc[i][j0+1] + bias[n+1];
            v.z = acc[i][j0+2] + bias[n+2];
            v.w = acc[i][j0+3] + bias[n+3];
            *(float4*)&OUT[((size_t)(b*HEADS + h)*SEQ + s)*HDIM + hd] = v;
        }
    }
}

// =====================================================================
// Scores: S[b,h,q,k] = 0.125 * q·k.  64x64 tile, full K=64 depth in smem.
// Raw scaled scores written to AW; mask/zeroing handled by softmax pass.
// grid = (16 ktiles, 16 qtiles, 32 bh); upper-triangle tiles early-out.
// =====================================================================
__global__ __launch_bounds__(256)
void scores_kernel(float* __restrict__ AW)
{
    const int k0 = blockIdx.x * 64;
    const int q0 = blockIdx.y * 64;
    if (k0 > q0 + 63) return;                 // entirely above diagonal
    const int bh = blockIdx.z;

    __shared__ float Qs[64][68];              // [d][q]
    __shared__ float Ks[64][68];              // [d][k]
    const float* qb = g_q + (size_t)bh * SEQ * HDIM;
    const float* kb = g_k + (size_t)bh * SEQ * HDIM;
    const int tid = threadIdx.x;

#pragma unroll
    for (int i = 0; i < 4; i++) {
        int idx = tid + i*256;
        int r = idx >> 4, c = (idx & 15) * 4;
        float4 v = *(const float4*)(qb + (size_t)(q0+r)*HDIM + c);
        Qs[c+0][r]=v.x; Qs[c+1][r]=v.y; Qs[c+2][r]=v.z; Qs[c+3][r]=v.w;
        float4 w = *(const float4*)(kb + (size_t)(k0+r)*HDIM + c);
        Ks[c+0][r]=w.x; Ks[c+1][r]=w.y; Ks[c+2][r]=w.z; Ks[c+3][r]=w.w;
    }
    __syncthreads();

    const int ty = tid >> 4, tx = tid & 15;
    float acc[4][4];
#pragma unroll
    for (int i=0;i<4;i++)
#pragma unroll
        for (int j=0;j<4;j++) acc[i][j]=0.f;

#pragma unroll
    for (int d = 0; d < 64; d++) {
        float a[4], b[4];
        *(float4*)a = *(const float4*)&Qs[d][ty*4];
        *(float4*)b = *(const float4*)&Ks[d][tx*4];
#pragma unroll
        for (int i=0;i<4;i++)
#pragma unroll
            for (int j=0;j<4;j++) acc[i][j] += a[i]*b[j];
    }

    float* outp = AW + (size_t)bh * SEQ * SEQ;
#pragma unroll
    for (int i = 0; i < 4; i++) {
        int qq = q0 + ty*4 + i;
        float4 v;
        v.x = acc[i][0]*0.125f; v.y = acc[i][1]*0.125f;
        v.z = acc[i][2]*0.125f; v.w = acc[i][3]*0.125f;
        *(float4*)&outp[(size_t)qq*SEQ + k0 + tx*4] = v;
    }
}

// =====================================================================
// Softmax per row with causal mask; zeros out k>q. grid = 32768 rows.
// =====================================================================
__global__ __launch_bounds__(256)
void softmax_kernel(float* __restrict__ AW)
{
    __shared__ float buf[SEQ];
    __shared__ float red[256];
    const int row = blockIdx.x;
    const int L   = (row & (SEQ-1)) + 1;
    float* p = AW + (size_t)row * SEQ;
    const int tid = threadIdx.x;

    float m = -1e30f;
    for (int i = tid; i < L; i += 256) { float v = p[i]; buf[i] = v; m = fmaxf(m, v); }
    red[tid] = m; __syncthreads();
    for (int s = 128; s > 0; s >>= 1) { if (tid < s) red[tid] = fmaxf(red[tid], red[tid+s]); __syncthreads(); }
    m = red[0]; __syncthreads();

    float sum = 0.f;
    for (int i = tid; i < L; i += 256) { float e = expf(buf[i] - m); buf[i] = e; sum += e; }
    red[tid] = sum; __syncthreads();
    for (int s = 128; s > 0; s >>= 1) { if (tid < s) red[tid] += red[tid+s]; __syncthreads(); }
    const float inv = 1.f / red[0];

    for (int i = tid;     i < L;   i += 256) p[i] = buf[i] * inv;
    for (int i = L + tid; i < SEQ; i += 256) p[i] = 0.f;
}

// =====================================================================
// AV: O[b,s,h*64+hd] = sum_k W[b,h,q,k] * V[b,h,k,hd]
// 64 q-rows x 64 hd per block; causal K-loop truncation.
// grid = (16 qtiles, 32 bh)
// =====================================================================
__global__ __launch_bounds__(256)
void av_kernel(const float* __restrict__ AW, float* __restrict__ O)
{
    const int q0 = blockIdx.x * 64;
    const int bh = blockIdx.y;
    __shared__ float Ws[16][68];   // [k][q]
    __shared__ float Vs[16][68];   // [k][hd]
    const int tid = threadIdx.x;
    const int ty = tid >> 4, tx = tid & 15;
    const float* wb = AW  + (size_t)bh * SEQ * SEQ;
    const float* vb = g_v + (size_t)bh * SEQ * HDIM;
    const int kend = q0 + 64;        // weights are exactly 0 beyond this

    float acc[4][4];
#pragma unroll
    for (int i=0;i<4;i++)
#pragma unroll
        for (int j=0;j<4;j++) acc[i][j]=0.f;

    const int wr = tid >> 2,  wc = (tid & 3) * 4;   // W tile: 64q x 16k
    const int vr = tid >> 4,  vc = (tid & 15) * 4;  // V tile: 16k x 64hd

    for (int kt = 0; kt < kend; kt += 16) {
        float4 v = *(const float4*)(wb + (size_t)(q0+wr)*SEQ + kt + wc);
        Ws[wc+0][wr]=v.x; Ws[wc+1][wr]=v.y; Ws[wc+2][wr]=v.z; Ws[wc+3][wr]=v.w;
        *(float4*)&Vs[vr][vc] = *(const float4*)(vb + (size_t)(kt+vr)*HDIM + vc);
        __syncthreads();
#pragma unroll
        for (int kk = 0; kk < 16; kk++) {
            float a[4], b[4];
            *(float4*)a = *(const float4*)&Ws[kk][ty*4];
            *(float4*)b = *(const float4*)&Vs[kk][tx*4];
#pragma unroll
            for (int i=0;i<4;i++)
#pragma unroll
                for (int j=0;j<4;j++) acc[i][j] += a[i]*b[j];
        }
        __syncthreads();
    }

    const int b = bh >> 3, h = bh & 7;
#pragma unroll
    for (int i = 0; i < 4; i++) {
        int q = q0 + ty*4 + i;
        float4 v; v.x=acc[i][0]; v.y=acc[i][1]; v.z=acc[i][2]; v.w=acc[i][3];
        *(float4*)&O[(size_t)(b*SEQ + q)*DIM + h*HDIM + tx*4] = v;
    }
}

// =====================================================================
// LayerNorm over D=512: out = (x-mu)*rstd*g + b. 128 threads, float4 each.
// =====================================================================
__global__ __launch_bounds__(128)
void ln_kernel(const float* __restrict__ in, const float* __restrict__ gam,
               const float* __restrict__ bet, float* __restrict__ out)
{
    __shared__ float red[128];
    const int row = blockIdx.x, tid = threadIdx.x;
    float4 v = ((const float4*)(in + (size_t)row*DIM))[tid];

    red[tid] = v.x+v.y+v.z+v.w; __syncthreads();
    for (int s=64;s>0;s>>=1){ if (tid<s) red[tid]+=red[tid+s]; __syncthreads(); }
    const float mu = red[0] * (1.f/DIM); __syncthreads();

    float dx=v.x-mu, dy=v.y-mu, dz=v.z-mu, dw=v.w-mu;
    red[tid] = dx*dx+dy*dy+dz*dz+dw*dw; __syncthreads();
    for (int s=64;s>0;s>>=1){ if (tid<s) red[tid]+=red[tid+s]; __syncthreads(); }
    const float rstd = rsqrtf(red[0]*(1.f/DIM) + EPSLN);

    float4 gg = ((const float4*)gam)[tid];
    float4 bb = ((const float4*)bet)[tid];
    float4 o;
    o.x = dx*rstd*gg.x + bb.x; o.y = dy*rstd*gg.y + bb.y;
    o.z = dz*rstd*gg.z + bb.z; o.w = dw*rstd*gg.w + bb.w;
    ((float4*)(out + (size_t)row*DIM))[tid] = o;
}

// =====================================================================
// Final: glu = g[:512]*sigmoid(g[512:]); t = glu + h; out = LN2(t) + h
// =====================================================================
__global__ __launch_bounds__(128)
void final_kernel(const float* __restrict__ ln2g, const float* __restrict__ ln2b,
                  float* __restrict__ out)
{
    __shared__ float red[128];
    const int row = blockIdx.x, tid = threadIdx.x;
    float4 ga = ((const float4*)(g_g + (size_t)row*2*DIM))[tid];
    float4 gb = ((const float4*)(g_g + (size_t)row*2*DIM + DIM))[tid];
    float4 hh = ((const float4*)(g_h + (size_t)row*DIM))[tid];

    float4 t;
    t.x = ga.x / (1.f + expf(-gb.x)) + hh.x;
    t.y = ga.y / (1.f + expf(-gb.y)) + hh.y;
    t.z = ga.z / (1.f + expf(-gb.z)) + hh.z;
    t.w = ga.w / (1.f + expf(-gb.w)) + hh.w;

    red[tid] = t.x+t.y+t.z+t.w; __syncthreads();
    for (int s=64;s>0;s>>=1){ if (tid<s) red[tid]+=red[tid+s]; __syncthreads(); }
    const float mu = red[0] * (1.f/DIM); __syncthreads();

    float dx=t.x-mu, dy=t.y-mu, dz=t.z-mu, dw=t.w-mu;
    red[tid] = dx*dx+dy*dy+dz*dz+dw*dw; __syncthreads();
    for (int s=64;s>0;s>>=1){ if (tid<s) red[tid]+=red[tid+s]; __syncthreads(); }
    const float rstd = rsqrtf(red[0]*(1.f/DIM) + EPSLN);

    float4 gg = ((const float4*)ln2g)[tid];
    float4 bb = ((const float4*)ln2b)[tid];
    float4 o;
    o.x = dx*rstd*gg.x + bb.x + hh.x;
    o.y = dy*rstd*gg.y + bb.y + hh.y;
    o.z = dz*rstd*gg.z + bb.z + hh.z;
    o.w = dw*rstd*gg.w + bb.w + hh.w;
    ((float4*)(out + (size_t)row*DIM))[tid] = o;
}

// =====================================================================
// Host launch
// =====================================================================
static float* sym(const void* s) {
    void* p = nullptr;
    cudaGetSymbolAddress(&p, (const void*)s);
    return (float*)p;
}

extern "C" void kernel_launch(void* const* d_in, const int* in_sizes, int n_in,
                              void* d_out, int out_size)
{
    const float* x    = (const float*)d_in[0];
    const float* Wq   = (const float*)d_in[1];
    const float* bq   = (const float*)d_in[2];
    const float* Wk   = (const float*)d_in[3];
    const float* bk   = (const float*)d_in[4];
    const float* Wv   = (const float*)d_in[5];
    const float* bv   = (const float*)d_in[6];
    const float* Wo   = (const float*)d_in[7];
    const float* bo   = (const float*)d_in[8];
    const float* l1g  = (const float*)d_in[9];
    const float* l1b  = (const float*)d_in[10];
    const float* W1   = (const float*)d_in[11];
    const float* b1   = (const float*)d_in[12];
    const float* W2   = (const float*)d_in[13];
    const float* b2   = (const float*)d_in[14];
    const float* Wg   = (const float*)d_in[15];
    const float* bg   = (const float*)d_in[16];
    const float* l2g  = (const float*)d_in[17];
    const float* l2b  = (const float*)d_in[18];

    float* OUT = (float*)d_out;                         // (4,1024,512)
    float* AW  = OUT + (size_t)ROWS * DIM;              // (4,8,1024,1024)

    float* p_ao  = sym(g_ao);
    float* p_t1  = sym(g_t1);
    float* p_h   = sym(g_h);
    float* p_hid = sym(g_hid);
    float* p_h2  = sym(g_h2);
    float* p_g   = sym(g_g);

    // 1. Fused QKV projection -> g_q/g_k/g_v in (b,h,s,hd)
    qkv_kernel<<<dim3(12, 32), 256>>>(x, Wq, Wk, Wv, bq, bk, bv);

    // 2. Scores (raw, scaled) -> AW
    scores_kernel<<<dim3(16, 16, BH), 256>>>(AW);

    // 3. Causal softmax in place (zeros above-diagonal)
    softmax_kernel<<<BH * SEQ, 256>>>(AW);

    // 4. AV -> g_ao in (b,s,d)
    av_kernel<<<dim3(16, BH), 256>>>(AW, p_ao);

    // 5. Wo projection + residual x -> g_t1
    sgemm_kernel<2><<<dim3(DIM/128, ROWS/128), 256>>>(p_ao, Wo, bo, x, p_t1, ROWS, DIM, DIM);

    // 6. LN1 -> g_h
    ln_kernel<<<ROWS, 128>>>(p_t1, l1g, l1b, p_h);

    // 7. hid = elu(h@W1 + b1)
    sgemm_kernel<1><<<dim3(FF/128, ROWS/128), 256>>>(p_h, W1, b1, nullptr, p_hid, ROWS, FF, DIM);

    // 8. h2 = hid@W2 + b2
    sgemm_kernel<0><<<dim3(DIM/128, ROWS/128), 256>>>(p_hid, W2, b2, nullptr, p_h2, ROWS, DIM, FF);

    // 9. g = h2@Wg + bg
    sgemm_kernel<0><<<dim3((2*DIM)/128, ROWS/128), 256>>>(p_h2, Wg, bg, nullptr, p_g, ROWS, 2*DIM, DIM);

    // 10. GLU + LN2 + residual -> OUT
    final_kernel<<<ROWS, 128>>>(l2g, l2b, OUT);
}

// round 15
// speedup vs baseline: 1.8884x; 1.8884x over previous
#include <cuda_runtime.h>
#include <math.h>
#include <stdint.h>

// Problem constants
#define BATCH 4
#define SEQ   1024
#define DIM   512
#define HEADS 8
#define HDIM  64
#define FF    2048
#define ROWS  (BATCH*SEQ)          // 4096
#define BH    (BATCH*HEADS)        // 32
#define EPSLN 1e-5f

// ---------------- scratch (device globals; no allocation allowed) ----------------
__device__ float g_q  [BH*SEQ*HDIM];     // (b,h,s,hd)
__device__ float g_k  [BH*SEQ*HDIM];
__device__ float g_v  [BH*SEQ*HDIM];
__device__ float g_ao [ROWS*DIM];        // attn out in (b,s,d)
__device__ float g_t1 [ROWS*DIM];        // x + attn@Wo+bo
__device__ float g_h  [ROWS*DIM];        // LN1 output
__device__ float g_hid[ROWS*FF];         // elu(h@W1+b1)
__device__ float g_h2 [ROWS*DIM];        // hid@W2+b2
__device__ float g_g  [ROWS*2*DIM];      // h2@Wg+bg

// ---------------- tf32 helpers ----------------
__device__ __forceinline__ uint32_t tf32_of(float f) {
    uint32_t u;
    asm("cvt.rna.tf32.f32 %0, %1;" : "=r"(u) : "f"(f));
    return u;
}

__device__ __forceinline__ void mma_tf32(float c[4],
                                         uint32_t a0, uint32_t a1, uint32_t a2, uint32_t a3,
                                         uint32_t b0, uint32_t b1) {
    asm volatile(
        "mma.sync.aligned.m16n8k8.row.col.f32.tf32.tf32.f32 "
        "{%0,%1,%2,%3}, {%4,%5,%6,%7}, {%8,%9}, {%0,%1,%2,%3};"
        : "+f"(c[0]), "+f"(c[1]), "+f"(c[2]), "+f"(c[3])
        : "r"(a0), "r"(a1), "r"(a2), "r"(a3), "r"(b0), "r"(b1));
}

// Smem strides chosen for conflict-free fragment loads:
//   A: [128][36]  -> frag addr (36*m+k)%32 = (4g+tg)%32, bijective over warp
//   B: [32][136]  -> frag addr (136*k+n)%32 = (8tg+g)%32, bijective over warp
#define ASTRIDE 36
#define BSTRIDE 136

// =====================================================================
// TF32 tensor-core GEMM: C[M,N] = A[M,K] @ B[K,N] + bias
// 128x128x32 CTA tile, 256 threads = 8 warps (2 x 4), warp tile 64x32.
// EPI: 0=plain, 1=ELU, 2=+resid
// =====================================================================
template<int EPI>
__global__ __launch_bounds__(256, 2)
void tgemm_kernel(const float* __restrict__ A, const float* __restrict__ B,
                  const float* __restrict__ bias, const float* __restrict__ resid,
                  float* __restrict__ C, int M, int N, int K)
{
    __shared__ uint32_t As[128 * ASTRIDE];
    __shared__ uint32_t Bs[32 * BSTRIDE];

    const int tid  = threadIdx.x;
    const int row0 = blockIdx.y * 128;
    const int col0 = blockIdx.x * 128;
    const int wid  = tid >> 5;
    const int lane = tid & 31;
    const int wm   = wid >> 2;      // 0..1  (64 rows each)
    const int wn   = wid & 3;       // 0..3  (32 cols each)
    const int g    = lane >> 2;     // 0..7
    const int tg   = lane & 3;      // 0..3

    // gmem->smem assignments
    const int a_r = tid >> 3;            // 0..31 (+i*32)
    const int a_c = (tid & 7) * 4;       // 0..28
    const int b_r = tid >> 5;            // 0..7  (+i*8)
    const int b_c = (tid & 31) * 4;      // 0..124

    float acc[4][4][4];
#pragma unroll
    for (int mt = 0; mt < 4; mt++)
#pragma unroll
        for (int nt = 0; nt < 4; nt++)
#pragma unroll
            for (int e = 0; e < 4; e++) acc[mt][nt][e] = 0.f;

    for (int kt = 0; kt < K; kt += 32) {
        // load A tile (128x32) with tf32 conversion
#pragma unroll
        for (int i = 0; i < 4; i++) {
            int r = a_r + i * 32;
            float4 v = *(const float4*)(A + (size_t)(row0 + r) * K + kt + a_c);
            uint4 u = make_uint4(tf32_of(v.x), tf32_of(v.y), tf32_of(v.z), tf32_of(v.w));
            *(uint4*)&As[r * ASTRIDE + a_c] = u;
        }
        // load B tile (32x128)
#pragma unroll
        for (int i = 0; i < 4; i++) {
            int r = b_r + i * 8;
            float4 v = *(const float4*)(B + (size_t)(kt + r) * N + col0 + b_c);
            uint4 u = make_uint4(tf32_of(v.x), tf32_of(v.y), tf32_of(v.z), tf32_of(v.w));
            *(uint4*)&Bs[r * BSTRIDE + b_c] = u;
        }
        __syncthreads();

#pragma unroll
        for (int kk = 0; kk < 4; kk++) {
            const int k0 = kk * 8;
            uint32_t af[4][4], bf[4][2];
#pragma unroll
            for (int mt = 0; mt < 4; mt++) {
                int bm = wm * 64 + mt * 16;
                af[mt][0] = As[(bm + g    ) * ASTRIDE + k0 + tg    ];
                af[mt][1] = As[(bm + g + 8) * ASTRIDE + k0 + tg    ];
                af[mt][2] = As[(bm + g    ) * ASTRIDE + k0 + tg + 4];
                af[mt][3] = As[(bm + g + 8) * ASTRIDE + k0 + tg + 4];
            }
#pragma unroll
            for (int nt = 0; nt < 4; nt++) {
                int bn = wn * 32 + nt * 8;
                bf[nt][0] = Bs[(k0 + tg    ) * BSTRIDE + bn + g];
                bf[nt][1] = Bs[(k0 + tg + 4) * BSTRIDE + bn + g];
            }
#pragma unroll
            for (int mt = 0; mt < 4; mt++)
#pragma unroll
                for (int nt = 0; nt < 4; nt++)
                    mma_tf32(acc[mt][nt], af[mt][0], af[mt][1], af[mt][2], af[mt][3],
                             bf[nt][0], bf[nt][1]);
        }
        __syncthreads();
    }

    // epilogue
#pragma unroll
    for (int mt = 0; mt < 4; mt++) {
#pragma unroll
        for (int nt = 0; nt < 4; nt++) {
            int r0 = row0 + wm * 64 + mt * 16 + g;
            int c  = col0 + wn * 32 + nt * 8 + tg * 2;
            float b0 = bias[c], b1 = bias[c + 1];
#pragma unroll
            for (int half = 0; half < 2; half++) {
                int r = r0 + half * 8;
                float v0 = acc[mt][nt][half * 2 + 0] + b0;
                float v1 = acc[mt][nt][half * 2 + 1] + b1;
                if (EPI == 1) {
                    v0 = v0 > 0.f ? v0 : expm1f(v0);
                    v1 = v1 > 0.f ? v1 : expm1f(v1);
                }
                if (EPI == 2) {
                    float2 rr = *(const float2*)&resid[(size_t)r * N + c];
                    v0 += rr.x; v1 += rr.y;
                }
                float2 o; o.x = v0; o.y = v1;
                *(float2*)&C[(size_t)r * N + c] = o;
            }
        }
    }
}

// =====================================================================
// TF32 fused QKV GEMM: x(4096,512) @ {Wq,Wk,Wv}, remap to (b,h,s,hd)
// grid = (12, 32): bx 0-3 -> Q, 4-7 -> K, 8-11 -> V
// =====================================================================
__global__ __launch_bounds__(256, 2)
void qkv_kernel(const float* __restrict__ A,
                const float* __restrict__ Wq, const float* __restrict__ Wk,
                const float* __restrict__ Wv,
                const float* __restrict__ bq, const float* __restrict__ bk,
                const float* __restrict__ bv)
{
    __shared__ uint32_t As[128 * ASTRIDE];
    __shared__ uint32_t Bs[32 * BSTRIDE];

    const int tid  = threadIdx.x;
    const int n0   = blockIdx.x * 128;
    const int which = n0 >> 9;                      // 0,1,2
    const float* W    = (which == 0) ? Wq : (which == 1) ? Wk : Wv;
    const float* bias = (which == 0) ? bq : (which == 1) ? bk : bv;
    float*       OUT  = (which == 0) ? g_q : (which == 1) ? g_k : g_v;
    const int nloc0 = n0 & 511;
    const int row0  = blockIdx.y * 128;

    const int wid  = tid >> 5;
    const int lane = tid & 31;
    const int wm   = wid >> 2;
    const int wn   = wid & 3;
    const int g    = lane >> 2;
    const int tg   = lane & 3;

    const int a_r = tid >> 3;
    const int a_c = (tid & 7) * 4;
    const int b_r = tid >> 5;
    const int b_c = (tid & 31) * 4;

    float acc[4][4][4];
#pragma unroll
    for (int mt = 0; mt < 4; mt++)
#pragma unroll
        for (int nt = 0; nt < 4; nt++)
#pragma unroll
            for (int e = 0; e < 4; e++) acc[mt][nt][e] = 0.f;

    for (int kt = 0; kt < DIM; kt += 32) {
#pragma unroll
        for (int i = 0; i < 4; i++) {
            int r = a_r + i * 32;
            float4 v = *(const float4*)(A + (size_t)(row0 + r) * DIM + kt + a_c);
            uint4 u = make_uint4(tf32_of(v.x), tf32_of(v.y), tf32_of(v.z), tf32_of(v.w));
            *(uint4*)&As[r * ASTRIDE + a_c] = u;
        }
#pragma unroll
        for (int i = 0; i < 4; i++) {
            int r = b_r + i * 8;
            float4 v = *(const float4*)(W + (size_t)(kt + r) * DIM + nloc0 + b_c);
            uint4 u = make_uint4(tf32_of(v.x), tf32_of(v.y), tf32_of(v.z), tf32_of(v.w));
            *(uint4*)&Bs[r * BSTRIDE + b_c] = u;
        }
        __syncthreads();

#pragma unroll
        for (int kk = 0; kk < 4; kk++) {
            const int k0 = kk * 8;
            uint32_t af[4][4], bf[4][2];
#pragma unroll
            for (int mt = 0; mt < 4; mt++) {
                int bm = wm * 64 + mt * 16;
                af[mt][0] = As[(bm + g    ) * ASTRIDE + k0 + tg    ];
                af[mt][1] = As[(bm + g + 8) * ASTRIDE + k0 + tg    ];
                af[mt][2] = As[(bm + g    ) * ASTRIDE + k0 + tg + 4];
                af[mt][3] = As[(bm + g + 8) * ASTRIDE + k0 + tg + 4];
            }
#pragma unroll
            for (int nt = 0; nt < 4; nt++) {
                int bn = wn * 32 + nt * 8;
                bf[nt][0] = Bs[(k0 + tg    ) * BSTRIDE + bn + g];
                bf[nt][1] = Bs[(k0 + tg + 4) * BSTRIDE + bn + g];
            }
#pragma unroll
            for (int mt = 0; mt < 4; mt++)
#pragma unroll
                for (int nt = 0; nt < 4; nt++)
                    mma_tf32(acc[mt][nt], af[mt][0], af[mt][1], af[mt][2], af[mt][3],
                             bf[nt][0], bf[nt][1]);
        }
        __syncthreads();
    }

    // epilogue with (b,h,s,hd) remap
#pragma unroll
    for (int mt = 0; mt < 4; mt++) {
#pragma unroll
        for (int nt = 0; nt < 4; nt++) {
            int n  = nloc0 + wn * 32 + nt * 8 + tg * 2;   // within [0,512)
            int h  = n >> 6, hd = n & 63;                 // same h for both cols
            float b0 = bias[n], b1 = bias[n + 1];
#pragma unroll
            for (int half = 0; half < 2; half++) {
                int m = row0 + wm * 64 + mt * 16 + g + half * 8;
                int b = m >> 10, s = m & 1023;
                float2 o;
                o.x = acc[mt][nt][half * 2 + 0] + b0;
                o.y = acc[mt][nt][half * 2 + 1] + b1;
                *(float2*)&OUT[((size_t)(b * HEADS + h) * SEQ + s) * HDIM + hd] = o;
            }
        }
    }
}

// =====================================================================
// Scores: S[b,h,q,k] = 0.125 * q·k.  64x64 tile, full K=64 depth in smem.
// grid = (16 ktiles, 16 qtiles, 32 bh); upper-triangle tiles early-out.
// =====================================================================
__global__ __launch_bounds__(256)
void scores_kernel(float* __restrict__ AW)
{
    const int k0 = blockIdx.x * 64;
    const int q0 = blockIdx.y * 64;
    if (k0 > q0 + 63) return;                 // entirely above diagonal
    const int bh = blockIdx.z;

    __shared__ float Qs[64][68];              // [d][q]
    __shared__ float Ks[64][68];              // [d][k]
    const float* qb = g_q + (size_t)bh * SEQ * HDIM;
    const float* kb = g_k + (size_t)bh * SEQ * HDIM;
    const int tid = threadIdx.x;

#pragma unroll
    for (int i = 0; i < 4; i++) {
        int idx = tid + i*256;
        int r = idx >> 4, c = (idx & 15) * 4;
        float4 v = *(const float4*)(qb + (size_t)(q0+r)*HDIM + c);
        Qs[c+0][r]=v.x; Qs[c+1][r]=v.y; Qs[c+2][r]=v.z; Qs[c+3][r]=v.w;
        float4 w = *(const float4*)(kb + (size_t)(k0+r)*HDIM + c);
        Ks[c+0][r]=w.x; Ks[c+1][r]=w.y; Ks[c+2][r]=w.z; Ks[c+3][r]=w.w;
    }
    __syncthreads();

    const int ty = tid >> 4, tx = tid & 15;
    float acc[4][4];
#pragma unroll
    for (int i=0;i<4;i++)
#pragma unroll
        for (int j=0;j<4;j++) acc[i][j]=0.f;

#pragma unroll
    for (int d = 0; d < 64; d++) {
        float a[4], b[4];
        *(float4*)a = *(const float4*)&Qs[d][ty*4];
        *(float4*)b = *(const float4*)&Ks[d][tx*4];
#pragma unroll
        for (int i=0;i<4;i++)
#pragma unroll
            for (int j=0;j<4;j++) acc[i][j] += a[i]*b[j];
    }

    float* outp = AW + (size_t)bh * SEQ * SEQ;
#pragma unroll
    for (int i = 0; i < 4; i++) {
        int qq = q0 + ty*4 + i;
        float4 v;
        v.x = acc[i][0]*0.125f; v.y = acc[i][1]*0.125f;
        v.z = acc[i][2]*0.125f; v.w = acc[i][3]*0.125f;
        *(float4*)&outp[(size_t)qq*SEQ + k0 + tx*4] = v;
    }
}

// =====================================================================
// Softmax per row with causal mask; zeros out k>q. grid = 32768 rows.
// =====================================================================
__global__ __launch_bounds__(256)
void softmax_kernel(float* __restrict__ AW)
{
    __shared__ float buf[SEQ];
    __shared__ float red[256];
    const int row = blockIdx.x;
    const int L   = (row & (SEQ-1)) + 1;
    float* p = AW + (size_t)row * SEQ;
    const int tid = threadIdx.x;

    float m = -1e30f;
    for (int i = tid; i < L; i += 256) { float v = p[i]; buf[i] = v; m = fmaxf(m, v); }
    red[tid] = m; __syncthreads();
    for (int s = 128; s > 0; s >>= 1) { if (tid < s) red[tid] = fmaxf(red[tid], red[tid+s]); __syncthreads(); }
    m = red[0]; __syncthreads();

    float sum = 0.f;
    for (int i = tid; i < L; i += 256) { float e = expf(buf[i] - m); buf[i] = e; sum += e; }
    red[tid] = sum; __syncthreads();
    for (int s = 128; s > 0; s >>= 1) { if (tid < s) red[tid] += red[tid+s]; __syncthreads(); }
    const float inv = 1.f / red[0];

    for (int i = tid;     i < L;   i += 256) p[i] = buf[i] * inv;
    for (int i = L + tid; i < SEQ; i += 256) p[i] = 0.f;
}

// =====================================================================
// AV: O[b,s,h*64+hd] = sum_k W[b,h,q,k] * V[b,h,k,hd]
// 64 q-rows x 64 hd per block; causal K-loop truncation.
// grid = (16 qtiles, 32 bh)
// =====================================================================
__global__ __launch_bounds__(256)
void av_kernel(const float* __restrict__ AW, float* __restrict__ O)
{
    const int q0 = blockIdx.x * 64;
    const int bh = blockIdx.y;
    __shared__ float Ws[16][68];   // [k][q]
    __shared__ float Vs[16][68];   // [k][hd]
    const int tid = threadIdx.x;
    const int ty = tid >> 4, tx = tid & 15;
    const float* wb = AW  + (size_t)bh * SEQ * SEQ;
    const float* vb = g_v + (size_t)bh * SEQ * HDIM;
    const int kend = q0 + 64;        // weights are exactly 0 beyond this

    float acc[4][4];
#pragma unroll
    for (int i=0;i<4;i++)
#pragma unroll
        for (int j=0;j<4;j++) acc[i][j]=0.f;

    const int wr = tid >> 2,  wc = (tid & 3) * 4;   // W tile: 64q x 16k
    const int vr = tid >> 4,  vc = (tid & 15) * 4;  // V tile: 16k x 64hd

    for (int kt = 0; kt < kend; kt += 16) {
        float4 v = *(const float4*)(wb + (size_t)(q0+wr)*SEQ + kt + wc);
        Ws[wc+0][wr]=v.x; Ws[wc+1][wr]=v.y; Ws[wc+2][wr]=v.z; Ws[wc+3][wr]=v.w;
        *(float4*)&Vs[vr][vc] = *(const float4*)(vb + (size_t)(kt+vr)*HDIM + vc);
        __syncthreads();
#pragma unroll
        for (int kk = 0; kk < 16; kk++) {
            float a[4], b[4];
            *(float4*)a = *(const float4*)&Ws[kk][ty*4];
            *(float4*)b = *(const float4*)&Vs[kk][tx*4];
#pragma unroll
            for (int i=0;i<4;i++)
#pragma unroll
                for (int j=0;j<4;j++) acc[i][j] += a[i]*b[j];
        }
        __syncthreads();
    }

    const int b = bh >> 3, h = bh & 7;
#pragma unroll
    for (int i = 0; i < 4; i++) {
        int q = q0 + ty*4 + i;
        float4 v; v.x=acc[i][0]; v.y=acc[i][1]; v.z=acc[i][2]; v.w=acc[i][3];
        *(float4*)&O[(size_t)(b*SEQ + q)*DIM + h*HDIM + tx*4] = v;
    }
}

// =====================================================================
// LayerNorm over D=512: out = (x-mu)*rstd*g + b. 128 threads, float4 each.
// =====================================================================
__global__ __launch_bounds__(128)
void ln_kernel(const float* __restrict__ in, const float* __restrict__ gam,
               const float* __restrict__ bet, float* __restrict__ out)
{
    __shared__ float red[128];
    const int row = blockIdx.x, tid = threadIdx.x;
    float4 v = ((const float4*)(in + (size_t)row*DIM))[tid];

    red[tid] = v.x+v.y+v.z+v.w; __syncthreads();
    for (int s=64;s>0;s>>=1){ if (tid<s) red[tid]+=red[tid+s]; __syncthreads(); }
    const float mu = red[0] * (1.f/DIM); __syncthreads();

    float dx=v.x-mu, dy=v.y-mu, dz=v.z-mu, dw=v.w-mu;
    red[tid] = dx*dx+dy*dy+dz*dz+dw*dw; __syncthreads();
    for (int s=64;s>0;s>>=1){ if (tid<s) red[tid]+=red[tid+s]; __syncthreads(); }
    const float rstd = rsqrtf(red[0]*(1.f/DIM) + EPSLN);

    float4 gg = ((const float4*)gam)[tid];
    float4 bb = ((const float4*)bet)[tid];
    float4 o;
    o.x = dx*rstd*gg.x + bb.x; o.y = dy*rstd*gg.y + bb.y;
    o.z = dz*rstd*gg.z + bb.z; o.w = dw*rstd*gg.w + bb.w;
    ((float4*)(out + (size_t)row*DIM))[tid] = o;
}

// =====================================================================
// Final: glu = g[:512]*sigmoid(g[512:]); t = glu + h; out = LN2(t) + h
// =====================================================================
__global__ __launch_bounds__(128)
void final_kernel(const float* __restrict__ ln2g, const float* __restrict__ ln2b,
                  float* __restrict__ out)
{
    __shared__ float red[128];
    const int row = blockIdx.x, tid = threadIdx.x;
    float4 ga = ((const float4*)(g_g + (size_t)row*2*DIM))[tid];
    float4 gb = ((const float4*)(g_g + (size_t)row*2*DIM + DIM))[tid];
    float4 hh = ((const float4*)(g_h + (size_t)row*DIM))[tid];

    float4 t;
    t.x = ga.x / (1.f + expf(-gb.x)) + hh.x;
    t.y = ga.y / (1.f + expf(-gb.y)) + hh.y;
    t.z = ga.z / (1.f + expf(-gb.z)) + hh.z;
    t.w = ga.w / (1.f + expf(-gb.w)) + hh.w;

    red[tid] = t.x+t.y+t.z+t.w; __syncthreads();
    for (int s=64;s>0;s>>=1){ if (tid<s) red[tid]+=red[tid+s]; __syncthreads(); }
    const float mu = red[0] * (1.f/DIM); __syncthreads();

    float dx=t.x-mu, dy=t.y-mu, dz=t.z-mu, dw=t.w-mu;
    red[tid] = dx*dx+dy*dy+dz*dz+dw*dw; __syncthreads();
    for (int s=64;s>0;s>>=1){ if (tid<s) red[tid]+=red[tid+s]; __syncthreads(); }
    const float rstd = rsqrtf(red[0]*(1.f/DIM) + EPSLN);

    float4 gg = ((const float4*)ln2g)[tid];
    float4 bb = ((const float4*)ln2b)[tid];
    float4 o;
    o.x = dx*rstd*gg.x + bb.x + hh.x;
    o.y = dy*rstd*gg.y + bb.y + hh.y;
    o.z = dz*rstd*gg.z + bb.z + hh.z;
    o.w = dw*rstd*gg.w + bb.w + hh.w;
    ((float4*)(out + (size_t)row*DIM))[tid] = o;
}

// =====================================================================
// Host launch
// =====================================================================
static float* sym(const void* s) {
    void* p = nullptr;
    cudaGetSymbolAddress(&p, (const void*)s);
    return (float*)p;
}

extern "C" void kernel_launch(void* const* d_in, const int* in_sizes, int n_in,
                              void* d_out, int out_size)
{
    const float* x    = (const float*)d_in[0];
    const float* Wq   = (const float*)d_in[1];
    const float* bq   = (const float*)d_in[2];
    const float* Wk   = (const float*)d_in[3];
    const float* bk   = (const float*)d_in[4];
    const float* Wv   = (const float*)d_in[5];
    const float* bv   = (const float*)d_in[6];
    const float* Wo   = (const float*)d_in[7];
    const float* bo   = (const float*)d_in[8];
    const float* l1g  = (const float*)d_in[9];
    const float* l1b  = (const float*)d_in[10];
    const float* W1   = (const float*)d_in[11];
    const float* b1   = (const float*)d_in[12];
    const float* W2   = (const float*)d_in[13];
    const float* b2   = (const float*)d_in[14];
    const float* Wg   = (const float*)d_in[15];
    const float* bg   = (const float*)d_in[16];
    const float* l2g  = (const float*)d_in[17];
    const float* l2b  = (const float*)d_in[18];

    float* OUT = (float*)d_out;                         // (4,1024,512)
    float* AW  = OUT + (size_t)ROWS * DIM;              // (4,8,1024,1024)

    float* p_ao  = sym(g_ao);
    float* p_t1  = sym(g_t1);
    float* p_h   = sym(g_h);
    float* p_hid = sym(g_hid);
    float* p_h2  = sym(g_h2);
    float* p_g   = sym(g_g);

    // 1. Fused QKV projection (tf32 TC) -> g_q/g_k/g_v in (b,h,s,hd)
    qkv_kernel<<<dim3(12, 32), 256>>>(x, Wq, Wk, Wv, bq, bk, bv);

    // 2. Scores (raw, scaled) -> AW
    scores_kernel<<<dim3(16, 16, BH), 256>>>(AW);

    // 3. Causal softmax in place (zeros above-diagonal)
    softmax_kernel<<<BH * SEQ, 256>>>(AW);

    // 4. AV -> g_ao in (b,s,d)
    av_kernel<<<dim3(16, BH), 256>>>(AW, p_ao);

    // 5. Wo projection + residual x -> g_t1 (tf32 TC)
    tgemm_kernel<2><<<dim3(DIM/128, ROWS/128), 256>>>(p_ao, Wo, bo, x, p_t1, ROWS, DIM, DIM);

    // 6. LN1 -> g_h
    ln_kernel<<<ROWS, 128>>>(p_t1, l1g, l1b, p_h);

    // 7. hid = elu(h@W1 + b1) (tf32 TC)
    tgemm_kernel<1><<<dim3(FF/128, ROWS/128), 256>>>(p_h, W1, b1, nullptr, p_hid, ROWS, FF, DIM);

    // 8. h2 = hid@W2 + b2 (tf32 TC)
    tgemm_kernel<0><<<dim3(DIM/128, ROWS/128), 256>>>(p_hid, W2, b2, nullptr, p_h2, ROWS, DIM, FF);

    // 9. g = h2@Wg + bg (tf32 TC)
    tgemm_kernel<0><<<dim3((2*DIM)/128, ROWS/128), 256>>>(p_h2, Wg, bg, nullptr, p_g, ROWS, 2*DIM, DIM);

    // 10. GLU + LN2 + residual -> OUT
    final_kernel<<<ROWS, 128>>>(l2g, l2b, OUT);
}